// round 16
// baseline (speedup 1.0000x reference)
#include <cuda_runtime.h>
#include <cuda_bf16.h>
#include <cuda_fp16.h>
#include <math.h>
#include <cstdint>

#define NN 50000
#define NE 800000
#define INC 128
#define OUTC 64
#define HEADS 4
#define HC (HEADS * OUTC)   // 256
#define NEG_SLOPE 0.2f
#define ET (NE + NN)

// ---------------- scratch ------------------------------------------------------
__device__ __half g_hh[(size_t)NN * HC];    // projected features, fp16
__device__ float g_asrc[NN * HEADS];
__device__ float g_adst[NN * HEADS];
__device__ float g_den[NN * HEADS];
__device__ uint32_t g_wh[HC * INC / 2];     // W hi, bf16x2 pairs
__device__ uint32_t g_wl[HC * INC / 2];     // W lo, bf16x2 pairs
__device__ int   g_is64;

// ---------------- helpers ------------------------------------------------------
__device__ __forceinline__ float lrelu(float v) {
    return v >= 0.0f ? v : NEG_SLOPE * v;
}
__device__ __forceinline__ int edge_at(const void* ei, long long idx) {
    if (g_is64) return (int)((const long long*)ei)[idx];
    return ((const int*)ei)[idx];
}
__device__ __forceinline__ void red_add_v4(float* addr, float4 v) {
    asm volatile("red.global.add.v4.f32 [%0], {%1, %2, %3, %4};"
                 :: "l"(addr), "f"(v.x), "f"(v.y), "f"(v.z), "f"(v.w)
                 : "memory");
}
__device__ __forceinline__ uint32_t smem_to_u32(const void* p) {
    uint32_t a;
    asm("{ .reg .u64 t; cvta.to.shared.u64 t, %1; cvt.u32.u64 %0, t; }"
        : "=r"(a) : "l"(p));
    return a;
}
__device__ __forceinline__ uint32_t pack_hi2(float a, float b) {
    uint32_t r;
    asm("prmt.b32 %0, %1, %2, 0x7632;"
        : "=r"(r) : "r"(__float_as_uint(a)), "r"(__float_as_uint(b)));
    return r;
}
__device__ __forceinline__ uint32_t pack_lo2(float a, float b) {
    float la = a - __uint_as_float(__float_as_uint(a) & 0xFFFF0000u);
    float lb = b - __uint_as_float(__float_as_uint(b) & 0xFFFF0000u);
    uint32_t r;
    asm("cvt.rn.bf16x2.f32 %0, %1, %2;" : "=r"(r) : "f"(lb), "f"(la));
    return r;
}

#define LDSM_X4(r0, r1, r2, r3, a) \
    asm volatile("ldmatrix.sync.aligned.m8n8.x4.shared.b16 {%0,%1,%2,%3}, [%4];" \
                 : "=r"(r0), "=r"(r1), "=r"(r2), "=r"(r3) : "r"(a))

#define MMA_BF16(c, a0, a1, a2, a3, b0, b1) \
    asm volatile("mma.sync.aligned.m16n8k16.row.col.f32.bf16.bf16.f32 " \
                 "{%0,%1,%2,%3}, {%4,%5,%6,%7}, {%8,%9}, {%0,%1,%2,%3};" \
                 : "+f"((c)[0]), "+f"((c)[1]), "+f"((c)[2]), "+f"((c)[3]) \
                 : "r"(a0), "r"(a1), "r"(a2), "r"(a3), "r"(b0), "r"(b1))

// ---------------- 0) W pre-split + out zero (one launch) -------------------------
__global__ void prep_kernel(const float* __restrict__ W, float* __restrict__ out) {
    int i = blockIdx.x * blockDim.x + threadIdx.x;
    if (i < HC * INC / 2) {
        float a = W[2 * i], b = W[2 * i + 1];
        g_wh[i] = pack_hi2(a, b);
        g_wl[i] = pack_lo2(a, b);
    }
    if (i < NN * OUTC / 4)
        ((float4*)out)[i] = make_float4(0.f, 0.f, 0.f, 0.f);
}

// ---------------- 1) dtype detection -------------------------------------------
__global__ void detect_kernel(const int* __restrict__ ei_raw) {
    __shared__ int nz;
    if (threadIdx.x == 0) nz = 0;
    __syncthreads();
    int local = 0;
    for (int i = threadIdx.x; i < 4096; i += blockDim.x)
        if (ei_raw[2 * i + 1] != 0) local = 1;
    if (local) atomicOr(&nz, 1);
    __syncthreads();
    if (threadIdx.x == 0) g_is64 = (nz == 0) ? 1 : 0;
}

// ---------------- 2) HMMA split-bf16 GEMM + fused attention halves --------------
// CTA 256 thr: tile M=64 x N=256, K chunks of 32. Warp tile M=32 x N=64 (2x4).
// 2 CTAs/SM for cross-CTA phase overlap.
#define KCH 32
#define STR 40
#define AH_OFF 0
#define AL_OFF 5120                 // 64*40*2
#define BH_OFF 10240
#define BL_OFF 30720                // BH_OFF + 256*40*2
#define GSMEM 51200

__global__ __launch_bounds__(256, 2) void gemm_tc_kernel(
    const float* __restrict__ x,
    const float* __restrict__ att_src, const float* __restrict__ att_dst)
{
    {
        int zi = blockIdx.x * 256 + threadIdx.x;
        if (zi < NN * HEADS) g_den[zi] = 0.0f;
    }

    extern __shared__ char smem[];
    const uint32_t sbase = smem_to_u32(smem);
    const int tid = threadIdx.x;
    const int wid = tid >> 5;
    const int lane = tid & 31;
    const int rowBase = blockIdx.x * 64;

    const int wr = wid & 1;          // 2 row groups of 32
    const int wc = wid >> 1;         // 4 col groups of 64 (= head wc)
    const int R0 = wr * 32;
    const int N0 = wc * 64;

    const int lrow = lane & 7;
    const int quad = lane >> 3;

    const uint32_t addrA0 = sbase + AH_OFF +
        ((R0 + (quad & 1) * 8 + lrow) * STR + (quad >> 1) * 8) * 2;
    const uint32_t addrB0 = sbase + BH_OFF +
        ((N0 + (quad >> 1) * 8 + lrow) * STR + (quad & 1) * 8) * 2;

    float c[16][4];
#pragma unroll
    for (int t = 0; t < 16; t++)
#pragma unroll
        for (int q = 0; q < 4; q++) c[t][q] = 0.0f;

    const int xrow = tid >> 2;            // 0..63
    const int xkp = (tid & 3) * 8;        // 0,8,16,24
    const int wrow = tid;                 // 0..255: one W row per thread

    for (int kc = 0; kc < 4; kc++) {
        const int k0 = kc * KCH;
        // ---- x chunk: 64 rows x 32 k ----
        {
            int gr = rowBase + xrow;
            float4 v0 = make_float4(0.f, 0.f, 0.f, 0.f), v1 = v0;
            if (gr < NN) {
                const float4* xp = (const float4*)(x + (size_t)gr * INC + k0 + xkp);
                v0 = __ldg(&xp[0]);
                v1 = __ldg(&xp[1]);
            }
            uint4 hv, lv;
            hv.x = pack_hi2(v0.x, v0.y); hv.y = pack_hi2(v0.z, v0.w);
            hv.z = pack_hi2(v1.x, v1.y); hv.w = pack_hi2(v1.z, v1.w);
            lv.x = pack_lo2(v0.x, v0.y); lv.y = pack_lo2(v0.z, v0.w);
            lv.z = pack_lo2(v1.x, v1.y); lv.w = pack_lo2(v1.z, v1.w);
            char* p = smem + (xrow * STR + xkp) * 2;
            *(uint4*)(p + AH_OFF) = hv;
            *(uint4*)(p + AL_OFF) = lv;
        }
        // ---- W chunk: 256 rows x 32 k, pre-split bf16, straight copy ----
        {
            const int widx = wrow * 64 + (k0 >> 1);    // 16 uint32 = 32 k
            uint4 h0 = *(const uint4*)(g_wh + widx);
            uint4 h1 = *(const uint4*)(g_wh + widx + 4);
            uint4 h2 = *(const uint4*)(g_wh + widx + 8);
            uint4 h3 = *(const uint4*)(g_wh + widx + 12);
            uint4 l0 = *(const uint4*)(g_wl + widx);
            uint4 l1 = *(const uint4*)(g_wl + widx + 4);
            uint4 l2 = *(const uint4*)(g_wl + widx + 8);
            uint4 l3 = *(const uint4*)(g_wl + widx + 12);
            char* p = smem + wrow * STR * 2;
            *(uint4*)(p + BH_OFF) = h0;
            *(uint4*)(p + BH_OFF + 16) = h1;
            *(uint4*)(p + BH_OFF + 32) = h2;
            *(uint4*)(p + BH_OFF + 48) = h3;
            *(uint4*)(p + BL_OFF) = l0;
            *(uint4*)(p + BL_OFF + 16) = l1;
            *(uint4*)(p + BL_OFF + 32) = l2;
            *(uint4*)(p + BL_OFF + 48) = l3;
        }
        __syncthreads();

#pragma unroll
        for (int ks = 0; ks < 2; ks++) {
            uint32_t ah[2][4], al[2][4];
#pragma unroll
            for (int m = 0; m < 2; m++) {
                const uint32_t aA = addrA0 + ks * 32 + m * (16 * STR * 2);
                LDSM_X4(ah[m][0], ah[m][1], ah[m][2], ah[m][3], aA);
                LDSM_X4(al[m][0], al[m][1], al[m][2], al[m][3], aA + AL_OFF);
            }

            uint32_t aB = addrB0 + ks * 32;
#pragma unroll
            for (int tp = 0; tp < 4; tp++) {
                uint32_t bh0, bh1, bh2, bh3, bl0, bl1, bl2, bl3;
                LDSM_X4(bh0, bh1, bh2, bh3, aB);
                LDSM_X4(bl0, bl1, bl2, bl3, aB + (BL_OFF - BH_OFF));
#pragma unroll
                for (int m = 0; m < 2; m++) {
                    const int t = m * 8 + tp * 2;
                    MMA_BF16(c[t],     ah[m][0], ah[m][1], ah[m][2], ah[m][3], bh0, bh1);
                    MMA_BF16(c[t],     ah[m][0], ah[m][1], ah[m][2], ah[m][3], bl0, bl1);
                    MMA_BF16(c[t],     al[m][0], al[m][1], al[m][2], al[m][3], bh0, bh1);
                    MMA_BF16(c[t + 1], ah[m][0], ah[m][1], ah[m][2], ah[m][3], bh2, bh3);
                    MMA_BF16(c[t + 1], ah[m][0], ah[m][1], ah[m][2], ah[m][3], bl2, bl3);
                    MMA_BF16(c[t + 1], al[m][0], al[m][1], al[m][2], al[m][3], bh2, bh3);
                }
                aB += 16 * STR * 2;
            }
        }
        __syncthreads();
    }

    const int gid = lane >> 2;
    const int tig = lane & 3;

#pragma unroll
    for (int m = 0; m < 2; m++) {
        const int ra = rowBase + R0 + m * 16 + gid;
        const int rb = ra + 8;
        float sa = 0.f, sb = 0.f, da = 0.f, db = 0.f;
#pragma unroll
        for (int nt = 0; nt < 8; nt++) {
            const int t = m * 8 + nt;
            const int col = N0 + nt * 8 + tig * 2;
            float as0 = __ldg(&att_src[col]), as1 = __ldg(&att_src[col + 1]);
            float ad0 = __ldg(&att_dst[col]), ad1 = __ldg(&att_dst[col + 1]);
            sa += c[t][0] * as0 + c[t][1] * as1;
            sb += c[t][2] * as0 + c[t][3] * as1;
            da += c[t][0] * ad0 + c[t][1] * ad1;
            db += c[t][2] * ad0 + c[t][3] * ad1;
            if (ra < NN)
                *(__half2*)&g_hh[(size_t)ra * HC + col] = __floats2half2_rn(c[t][0], c[t][1]);
            if (rb < NN)
                *(__half2*)&g_hh[(size_t)rb * HC + col] = __floats2half2_rn(c[t][2], c[t][3]);
        }
        sa += __shfl_xor_sync(0xffffffffu, sa, 1);
        sa += __shfl_xor_sync(0xffffffffu, sa, 2);
        sb += __shfl_xor_sync(0xffffffffu, sb, 1);
        sb += __shfl_xor_sync(0xffffffffu, sb, 2);
        da += __shfl_xor_sync(0xffffffffu, da, 1);
        da += __shfl_xor_sync(0xffffffffu, da, 2);
        db += __shfl_xor_sync(0xffffffffu, db, 1);
        db += __shfl_xor_sync(0xffffffffu, db, 2);
        if (tig == 0) {
            if (ra < NN) {
                g_asrc[ra * HEADS + wc] = sa;
                g_adst[ra * HEADS + wc] = da;
            }
            if (rb < NN) {
                g_asrc[rb * HEADS + wc] = sb;
                g_adst[rb * HEADS + wc] = db;
            }
        }
    }
}

// ---------------- 3) edge pass: denominator accumulation ------------------------
__global__ void edge_kernel(const void* __restrict__ ei)
{
    int e = blockIdx.x * blockDim.x + threadIdx.x;
    if (e >= ET) return;
    int src, dst;
    if (e < NE) {
        src = edge_at(ei, e);
        dst = edge_at(ei, (long long)NE + e);
    } else {
        src = dst = e - NE;
    }
    float4 as = *(const float4*)&g_asrc[src * HEADS];
    float4 ad = *(const float4*)&g_adst[dst * HEADS];
    float4 ex;
    ex.x = __expf(lrelu(as.x + ad.x));
    ex.y = __expf(lrelu(as.y + ad.y));
    ex.z = __expf(lrelu(as.z + ad.z));
    ex.w = __expf(lrelu(as.w + ad.w));
    red_add_v4(&g_den[dst * HEADS], ex);
}

// ---------------- 4) weighted scatter: 8 lanes/edge, LDG.128, fp32 math ---------
__global__ __launch_bounds__(256) void scatter_kernel(
    const void* __restrict__ ei, float* __restrict__ out)
{
    const int gtid = blockIdx.x * blockDim.x + threadIdx.x;
    const int warp = gtid >> 5;
    const int lane = threadIdx.x & 31;
    const int eh = lane >> 3;
    const int j = lane & 7;
    const long long e = (long long)warp * 4 + eh;
    const bool valid = (e < ET);
    const long long ec = valid ? e : (ET - 1);

    int src = 0, dst = 0;
    float a0 = 0.f, a1 = 0.f, a2 = 0.f, a3 = 0.f;
    if (j == 0) {
        if (ec < NE) {
            src = edge_at(ei, ec);
            dst = edge_at(ei, (long long)NE + ec);
        } else {
            src = dst = (int)(ec - NE);
        }
        float4 as = *(const float4*)&g_asrc[src * HEADS];
        float4 ad = *(const float4*)&g_adst[dst * HEADS];
        float4 dn = *(const float4*)&g_den[dst * HEADS];
        a0 = 0.25f * __fdividef(__expf(lrelu(as.x + ad.x)), dn.x);
        a1 = 0.25f * __fdividef(__expf(lrelu(as.y + ad.y)), dn.y);
        a2 = 0.25f * __fdividef(__expf(lrelu(as.z + ad.z)), dn.z);
        a3 = 0.25f * __fdividef(__expf(lrelu(as.w + ad.w)), dn.w);
    }
    const int ls = eh << 3;
    src = __shfl_sync(0xffffffffu, src, ls);
    dst = __shfl_sync(0xffffffffu, dst, ls);
    a0 = __shfl_sync(0xffffffffu, a0, ls);
    a1 = __shfl_sync(0xffffffffu, a1, ls);
    a2 = __shfl_sync(0xffffffffu, a2, ls);
    a3 = __shfl_sync(0xffffffffu, a3, ls);

    const uint4* r4 = (const uint4*)(g_hh + (size_t)src * HC);
    uint4 u0 = r4[j];
    uint4 u1 = r4[8 + j];
    uint4 u2 = r4[16 + j];
    uint4 u3 = r4[24 + j];

    float v[8];
    float2 f;
    f = __half22float2(*(const __half2*)&u0.x); v[0] = a0 * f.x; v[1] = a0 * f.y;
    f = __half22float2(*(const __half2*)&u0.y); v[2] = a0 * f.x; v[3] = a0 * f.y;
    f = __half22float2(*(const __half2*)&u0.z); v[4] = a0 * f.x; v[5] = a0 * f.y;
    f = __half22float2(*(const __half2*)&u0.w); v[6] = a0 * f.x; v[7] = a0 * f.y;
    f = __half22float2(*(const __half2*)&u1.x); v[0] = fmaf(a1, f.x, v[0]); v[1] = fmaf(a1, f.y, v[1]);
    f = __half22float2(*(const __half2*)&u1.y); v[2] = fmaf(a1, f.x, v[2]); v[3] = fmaf(a1, f.y, v[3]);
    f = __half22float2(*(const __half2*)&u1.z); v[4] = fmaf(a1, f.x, v[4]); v[5] = fmaf(a1, f.y, v[5]);
    f = __half22float2(*(const __half2*)&u1.w); v[6] = fmaf(a1, f.x, v[6]); v[7] = fmaf(a1, f.y, v[7]);
    f = __half22float2(*(const __half2*)&u2.x); v[0] = fmaf(a2, f.x, v[0]); v[1] = fmaf(a2, f.y, v[1]);
    f = __half22float2(*(const __half2*)&u2.y); v[2] = fmaf(a2, f.x, v[2]); v[3] = fmaf(a2, f.y, v[3]);
    f = __half22float2(*(const __half2*)&u2.z); v[4] = fmaf(a2, f.x, v[4]); v[5] = fmaf(a2, f.y, v[5]);
    f = __half22float2(*(const __half2*)&u2.w); v[6] = fmaf(a2, f.x, v[6]); v[7] = fmaf(a2, f.y, v[7]);
    f = __half22float2(*(const __half2*)&u3.x); v[0] = fmaf(a3, f.x, v[0]); v[1] = fmaf(a3, f.y, v[1]);
    f = __half22float2(*(const __half2*)&u3.y); v[2] = fmaf(a3, f.x, v[2]); v[3] = fmaf(a3, f.y, v[3]);
    f = __half22float2(*(const __half2*)&u3.z); v[4] = fmaf(a3, f.x, v[4]); v[5] = fmaf(a3, f.y, v[5]);
    f = __half22float2(*(const __half2*)&u3.w); v[6] = fmaf(a3, f.x, v[6]); v[7] = fmaf(a3, f.y, v[7]);

    if (valid) {
        float* op = &out[(size_t)dst * OUTC + 8 * j];
        red_add_v4(op,     make_float4(v[0], v[1], v[2], v[3]));
        red_add_v4(op + 4, make_float4(v[4], v[5], v[6], v[7]));
    }
}

// ---------------- 5) finalize ------------------------------------------------------
__global__ void final_kernel(float* __restrict__ out, const float* __restrict__ bias)
{
    int i = blockIdx.x * blockDim.x + threadIdx.x;
    if (i >= NN * OUTC) return;
    float v = out[i] + bias[i & (OUTC - 1)];
    out[i] = fmaxf(v, 0.0f);
}

// ---------------- launch --------------------------------------------------------
extern "C" void kernel_launch(void* const* d_in, const int* in_sizes, int n_in,
                              void* d_out, int out_size)
{
    const float* x       = (const float*)d_in[0];
    const void*  ei      = d_in[1];
    const float* W       = (const float*)d_in[2];
    const float* att_src = (const float*)d_in[3];
    const float* att_dst = (const float*)d_in[4];
    const float* bias    = (const float*)d_in[5];
    float* out = (float*)d_out;

    cudaFuncSetAttribute(gemm_tc_kernel,
                         cudaFuncAttributeMaxDynamicSharedMemorySize, GSMEM);

    prep_kernel<<<(NN * OUTC / 4 + 255) / 256, 256>>>(W, out);        // idx 0
    detect_kernel<<<1, 256>>>((const int*)ei);                        // idx 1
    gemm_tc_kernel<<<(NN + 63) / 64, 256, GSMEM>>>(x, att_src, att_dst); // idx 2
    edge_kernel<<<(ET + 255) / 256, 256>>>(ei);                       // idx 3 (profiled)
    scatter_kernel<<<((size_t)ET * 8 + 255) / 256, 256>>>(ei, out);   // idx 4
    final_kernel<<<(NN * OUTC + 255) / 256, 256>>>(out, bias);        // idx 5
}

// round 17
// speedup vs baseline: 1.1362x; 1.1362x over previous
#include <cuda_runtime.h>
#include <cuda_bf16.h>
#include <cuda_fp16.h>
#include <math.h>
#include <cstdint>

#define NN 50000
#define NE 800000
#define INC 128
#define OUTC 64
#define HEADS 4
#define HC (HEADS * OUTC)   // 256
#define NEG_SLOPE 0.2f
#define ET (NE + NN)

// ---------------- scratch ------------------------------------------------------
__device__ __half g_hh[(size_t)NN * HC];    // projected features, fp16
__device__ float g_asrc[NN * HEADS];
__device__ float g_adst[NN * HEADS];
__device__ float g_den[NN * HEADS];
__device__ uint32_t g_wh[HC * INC / 2];     // W hi, bf16x2 pairs
__device__ uint32_t g_wl[HC * INC / 2];     // W lo, bf16x2 pairs
__device__ int   g_is64;

// ---------------- helpers ------------------------------------------------------
__device__ __forceinline__ float lrelu(float v) {
    return v >= 0.0f ? v : NEG_SLOPE * v;
}
__device__ __forceinline__ int edge_at(const void* ei, long long idx) {
    if (g_is64) return (int)((const long long*)ei)[idx];
    return ((const int*)ei)[idx];
}
__device__ __forceinline__ void red_add_v4(float* addr, float4 v) {
    asm volatile("red.global.add.v4.f32 [%0], {%1, %2, %3, %4};"
                 :: "l"(addr), "f"(v.x), "f"(v.y), "f"(v.z), "f"(v.w)
                 : "memory");
}
__device__ __forceinline__ uint32_t smem_to_u32(const void* p) {
    uint32_t a;
    asm("{ .reg .u64 t; cvta.to.shared.u64 t, %1; cvt.u32.u64 %0, t; }"
        : "=r"(a) : "l"(p));
    return a;
}
__device__ __forceinline__ uint32_t pack_hi2(float a, float b) {
    uint32_t r;
    asm("prmt.b32 %0, %1, %2, 0x7632;"
        : "=r"(r) : "r"(__float_as_uint(a)), "r"(__float_as_uint(b)));
    return r;
}
__device__ __forceinline__ uint32_t pack_lo2(float a, float b) {
    float la = a - __uint_as_float(__float_as_uint(a) & 0xFFFF0000u);
    float lb = b - __uint_as_float(__float_as_uint(b) & 0xFFFF0000u);
    uint32_t r;
    asm("cvt.rn.bf16x2.f32 %0, %1, %2;" : "=r"(r) : "f"(lb), "f"(la));
    return r;
}
__device__ __forceinline__ void cp_async16(uint32_t smem_dst, const void* gsrc) {
    asm volatile("cp.async.ca.shared.global [%0], [%1], 16;"
                 :: "r"(smem_dst), "l"(gsrc) : "memory");
}

#define LDSM_X4(r0, r1, r2, r3, a) \
    asm volatile("ldmatrix.sync.aligned.m8n8.x4.shared.b16 {%0,%1,%2,%3}, [%4];" \
                 : "=r"(r0), "=r"(r1), "=r"(r2), "=r"(r3) : "r"(a))

#define MMA_BF16(c, a0, a1, a2, a3, b0, b1) \
    asm volatile("mma.sync.aligned.m16n8k16.row.col.f32.bf16.bf16.f32 " \
                 "{%0,%1,%2,%3}, {%4,%5,%6,%7}, {%8,%9}, {%0,%1,%2,%3};" \
                 : "+f"((c)[0]), "+f"((c)[1]), "+f"((c)[2]), "+f"((c)[3]) \
                 : "r"(a0), "r"(a1), "r"(a2), "r"(a3), "r"(b0), "r"(b1))

// ---------------- 0) W pre-split --------------------------------------------------
__global__ void prep_kernel(const float* __restrict__ W) {
    int i = blockIdx.x * blockDim.x + threadIdx.x;
    if (i < HC * INC / 2) {
        float a = W[2 * i], b = W[2 * i + 1];
        g_wh[i] = pack_hi2(a, b);
        g_wl[i] = pack_lo2(a, b);
    }
}

// ---------------- 1) dtype detection -------------------------------------------
__global__ void detect_kernel(const int* __restrict__ ei_raw) {
    __shared__ int nz;
    if (threadIdx.x == 0) nz = 0;
    __syncthreads();
    int local = 0;
    for (int i = threadIdx.x; i < 4096; i += blockDim.x)
        if (ei_raw[2 * i + 1] != 0) local = 1;
    if (local) atomicOr(&nz, 1);
    __syncthreads();
    if (threadIdx.x == 0) g_is64 = (nz == 0) ? 1 : 0;
}

// ---------------- 2) HMMA split-bf16 GEMM + fused attention halves --------------
// CTA 512 thr: tile M=128 x N=256, K chunks of 32. Warp tile M=32 x N=64 (4x4).
// W tiles fetched with cp.async from pre-split bf16; x converted inline.
#define KCH 32
#define STR 40
#define AH_OFF 0
#define AL_OFF 10240
#define BH_OFF 20480
#define BL_OFF 40960
#define GSMEM 61440

__global__ __launch_bounds__(512) void gemm_tc_kernel(
    const float* __restrict__ x,
    const float* __restrict__ att_src, const float* __restrict__ att_dst)
{
    {
        int zi = blockIdx.x * 512 + threadIdx.x;
        if (zi < NN * HEADS) g_den[zi] = 0.0f;
    }

    extern __shared__ char smem[];
    const uint32_t sbase = smem_to_u32(smem);
    const int tid = threadIdx.x;
    const int wid = tid >> 5;
    const int lane = tid & 31;
    const int rowBase = blockIdx.x * 128;

    const int wr = wid & 3;          // 4 row groups of 32
    const int wc = wid >> 2;         // 4 col groups of 64 (= head wc)
    const int R0 = wr * 32;
    const int N0 = wc * 64;

    const int lrow = lane & 7;
    const int quad = lane >> 3;

    const uint32_t addrA0 = sbase + AH_OFF +
        ((R0 + (quad & 1) * 8 + lrow) * STR + (quad >> 1) * 8) * 2;
    const uint32_t addrB0 = sbase + BH_OFF +
        ((N0 + (quad >> 1) * 8 + lrow) * STR + (quad & 1) * 8) * 2;

    float c[16][4];
#pragma unroll
    for (int t = 0; t < 16; t++)
#pragma unroll
        for (int q = 0; q < 4; q++) c[t][q] = 0.0f;

    const int xrow = tid >> 2;            // 0..127
    const int xkp = (tid & 3) * 8;        // 0,8,16,24
    const int wrow = tid >> 1;            // 0..255
    const int wkp = (tid & 1) * 16;       // 0,16 (16 k = 32 bytes)

    for (int kc = 0; kc < 4; kc++) {
        const int k0 = kc * KCH;
        // ---- W chunk via cp.async (pre-split bf16, no registers) ----
        {
            const uint32_t widx = wrow * 64 + ((k0 + wkp) >> 1);   // uint32 units
            const uint32_t sdst = sbase + (wrow * STR + wkp) * 2;
            cp_async16(sdst + BH_OFF,      g_wh + widx);
            cp_async16(sdst + BH_OFF + 16, g_wh + widx + 4);
            cp_async16(sdst + BL_OFF,      g_wl + widx);
            cp_async16(sdst + BL_OFF + 16, g_wl + widx + 4);
            asm volatile("cp.async.commit_group;" ::: "memory");
        }
        // ---- x chunk: load fp32, truncation split, STS.128 ----
        {
            int gr = rowBase + xrow;
            float4 v0 = make_float4(0.f, 0.f, 0.f, 0.f), v1 = v0;
            if (gr < NN) {
                const float4* xp = (const float4*)(x + (size_t)gr * INC + k0 + xkp);
                v0 = __ldg(&xp[0]);
                v1 = __ldg(&xp[1]);
            }
            uint4 hv, lv;
            hv.x = pack_hi2(v0.x, v0.y); hv.y = pack_hi2(v0.z, v0.w);
            hv.z = pack_hi2(v1.x, v1.y); hv.w = pack_hi2(v1.z, v1.w);
            lv.x = pack_lo2(v0.x, v0.y); lv.y = pack_lo2(v0.z, v0.w);
            lv.z = pack_lo2(v1.x, v1.y); lv.w = pack_lo2(v1.z, v1.w);
            char* p = smem + (xrow * STR + xkp) * 2;
            *(uint4*)(p + AH_OFF) = hv;
            *(uint4*)(p + AL_OFF) = lv;
        }
        asm volatile("cp.async.wait_group 0;" ::: "memory");
        __syncthreads();

#pragma unroll
        for (int ks = 0; ks < 2; ks++) {
            uint32_t ah[2][4], al[2][4];
#pragma unroll
            for (int m = 0; m < 2; m++) {
                const uint32_t aA = addrA0 + ks * 32 + m * (16 * STR * 2);
                LDSM_X4(ah[m][0], ah[m][1], ah[m][2], ah[m][3], aA);
                LDSM_X4(al[m][0], al[m][1], al[m][2], al[m][3], aA + AL_OFF);
            }

            uint32_t aB = addrB0 + ks * 32;
#pragma unroll
            for (int tp = 0; tp < 4; tp++) {
                uint32_t bh0, bh1, bh2, bh3, bl0, bl1, bl2, bl3;
                LDSM_X4(bh0, bh1, bh2, bh3, aB);
                LDSM_X4(bl0, bl1, bl2, bl3, aB + (BL_OFF - BH_OFF));
#pragma unroll
                for (int m = 0; m < 2; m++) {
                    const int t = m * 8 + tp * 2;
                    MMA_BF16(c[t],     ah[m][0], ah[m][1], ah[m][2], ah[m][3], bh0, bh1);
                    MMA_BF16(c[t],     ah[m][0], ah[m][1], ah[m][2], ah[m][3], bl0, bl1);
                    MMA_BF16(c[t],     al[m][0], al[m][1], al[m][2], al[m][3], bh0, bh1);
                    MMA_BF16(c[t + 1], ah[m][0], ah[m][1], ah[m][2], ah[m][3], bh2, bh3);
                    MMA_BF16(c[t + 1], ah[m][0], ah[m][1], ah[m][2], ah[m][3], bl2, bl3);
                    MMA_BF16(c[t + 1], al[m][0], al[m][1], al[m][2], al[m][3], bh2, bh3);
                }
                aB += 16 * STR * 2;
            }
        }
        __syncthreads();
    }

    const int gid = lane >> 2;
    const int tig = lane & 3;

#pragma unroll
    for (int m = 0; m < 2; m++) {
        const int ra = rowBase + R0 + m * 16 + gid;
        const int rb = ra + 8;
        float sa = 0.f, sb = 0.f, da = 0.f, db = 0.f;
#pragma unroll
        for (int nt = 0; nt < 8; nt++) {
            const int t = m * 8 + nt;
            const int col = N0 + nt * 8 + tig * 2;
            float as0 = __ldg(&att_src[col]), as1 = __ldg(&att_src[col + 1]);
            float ad0 = __ldg(&att_dst[col]), ad1 = __ldg(&att_dst[col + 1]);
            sa += c[t][0] * as0 + c[t][1] * as1;
            sb += c[t][2] * as0 + c[t][3] * as1;
            da += c[t][0] * ad0 + c[t][1] * ad1;
            db += c[t][2] * ad0 + c[t][3] * ad1;
            if (ra < NN)
                *(__half2*)&g_hh[(size_t)ra * HC + col] = __floats2half2_rn(c[t][0], c[t][1]);
            if (rb < NN)
                *(__half2*)&g_hh[(size_t)rb * HC + col] = __floats2half2_rn(c[t][2], c[t][3]);
        }
        sa += __shfl_xor_sync(0xffffffffu, sa, 1);
        sa += __shfl_xor_sync(0xffffffffu, sa, 2);
        sb += __shfl_xor_sync(0xffffffffu, sb, 1);
        sb += __shfl_xor_sync(0xffffffffu, sb, 2);
        da += __shfl_xor_sync(0xffffffffu, da, 1);
        da += __shfl_xor_sync(0xffffffffu, da, 2);
        db += __shfl_xor_sync(0xffffffffu, db, 1);
        db += __shfl_xor_sync(0xffffffffu, db, 2);
        if (tig == 0) {
            if (ra < NN) {
                g_asrc[ra * HEADS + wc] = sa;
                g_adst[ra * HEADS + wc] = da;
            }
            if (rb < NN) {
                g_asrc[rb * HEADS + wc] = sb;
                g_adst[rb * HEADS + wc] = db;
            }
        }
    }
}

// ---------------- 3) edge pass: denominator accumulation + out zero -------------
__global__ void edge_kernel(const void* __restrict__ ei, float* __restrict__ out)
{
    int e = blockIdx.x * blockDim.x + threadIdx.x;
    if (e < NN * OUTC / 4)
        ((float4*)out)[e] = make_float4(0.f, 0.f, 0.f, 0.f);
    if (e >= ET) return;
    int src, dst;
    if (e < NE) {
        src = edge_at(ei, e);
        dst = edge_at(ei, (long long)NE + e);
    } else {
        src = dst = e - NE;
    }
    float4 as = *(const float4*)&g_asrc[src * HEADS];
    float4 ad = *(const float4*)&g_adst[dst * HEADS];
    float4 ex;
    ex.x = __expf(lrelu(as.x + ad.x));
    ex.y = __expf(lrelu(as.y + ad.y));
    ex.z = __expf(lrelu(as.z + ad.z));
    ex.w = __expf(lrelu(as.w + ad.w));
    red_add_v4(&g_den[dst * HEADS], ex);
}

// ---------------- 4) weighted scatter: 8 lanes/edge, LDG.128, fp32 math ---------
__global__ __launch_bounds__(256) void scatter_kernel(
    const void* __restrict__ ei, float* __restrict__ out)
{
    const int gtid = blockIdx.x * blockDim.x + threadIdx.x;
    const int warp = gtid >> 5;
    const int lane = threadIdx.x & 31;
    const int eh = lane >> 3;
    const int j = lane & 7;
    const long long e = (long long)warp * 4 + eh;
    const bool valid = (e < ET);
    const long long ec = valid ? e : (ET - 1);

    int src = 0, dst = 0;
    float a0 = 0.f, a1 = 0.f, a2 = 0.f, a3 = 0.f;
    if (j == 0) {
        if (ec < NE) {
            src = edge_at(ei, ec);
            dst = edge_at(ei, (long long)NE + ec);
        } else {
            src = dst = (int)(ec - NE);
        }
        float4 as = *(const float4*)&g_asrc[src * HEADS];
        float4 ad = *(const float4*)&g_adst[dst * HEADS];
        float4 dn = *(const float4*)&g_den[dst * HEADS];
        a0 = 0.25f * __fdividef(__expf(lrelu(as.x + ad.x)), dn.x);
        a1 = 0.25f * __fdividef(__expf(lrelu(as.y + ad.y)), dn.y);
        a2 = 0.25f * __fdividef(__expf(lrelu(as.z + ad.z)), dn.z);
        a3 = 0.25f * __fdividef(__expf(lrelu(as.w + ad.w)), dn.w);
    }
    const int ls = eh << 3;
    src = __shfl_sync(0xffffffffu, src, ls);
    dst = __shfl_sync(0xffffffffu, dst, ls);
    a0 = __shfl_sync(0xffffffffu, a0, ls);
    a1 = __shfl_sync(0xffffffffu, a1, ls);
    a2 = __shfl_sync(0xffffffffu, a2, ls);
    a3 = __shfl_sync(0xffffffffu, a3, ls);

    const uint4* r4 = (const uint4*)(g_hh + (size_t)src * HC);
    uint4 u0 = r4[j];
    uint4 u1 = r4[8 + j];
    uint4 u2 = r4[16 + j];
    uint4 u3 = r4[24 + j];

    float v[8];
    float2 f;
    f = __half22float2(*(const __half2*)&u0.x); v[0] = a0 * f.x; v[1] = a0 * f.y;
    f = __half22float2(*(const __half2*)&u0.y); v[2] = a0 * f.x; v[3] = a0 * f.y;
    f = __half22float2(*(const __half2*)&u0.z); v[4] = a0 * f.x; v[5] = a0 * f.y;
    f = __half22float2(*(const __half2*)&u0.w); v[6] = a0 * f.x; v[7] = a0 * f.y;
    f = __half22float2(*(const __half2*)&u1.x); v[0] = fmaf(a1, f.x, v[0]); v[1] = fmaf(a1, f.y, v[1]);
    f = __half22float2(*(const __half2*)&u1.y); v[2] = fmaf(a1, f.x, v[2]); v[3] = fmaf(a1, f.y, v[3]);
    f = __half22float2(*(const __half2*)&u1.z); v[4] = fmaf(a1, f.x, v[4]); v[5] = fmaf(a1, f.y, v[5]);
    f = __half22float2(*(const __half2*)&u1.w); v[6] = fmaf(a1, f.x, v[6]); v[7] = fmaf(a1, f.y, v[7]);
    f = __half22float2(*(const __half2*)&u2.x); v[0] = fmaf(a2, f.x, v[0]); v[1] = fmaf(a2, f.y, v[1]);
    f = __half22float2(*(const __half2*)&u2.y); v[2] = fmaf(a2, f.x, v[2]); v[3] = fmaf(a2, f.y, v[3]);
    f = __half22float2(*(const __half2*)&u2.z); v[4] = fmaf(a2, f.x, v[4]); v[5] = fmaf(a2, f.y, v[5]);
    f = __half22float2(*(const __half2*)&u2.w); v[6] = fmaf(a2, f.x, v[6]); v[7] = fmaf(a2, f.y, v[7]);
    f = __half22float2(*(const __half2*)&u3.x); v[0] = fmaf(a3, f.x, v[0]); v[1] = fmaf(a3, f.y, v[1]);
    f = __half22float2(*(const __half2*)&u3.y); v[2] = fmaf(a3, f.x, v[2]); v[3] = fmaf(a3, f.y, v[3]);
    f = __half22float2(*(const __half2*)&u3.z); v[4] = fmaf(a3, f.x, v[4]); v[5] = fmaf(a3, f.y, v[5]);
    f = __half22float2(*(const __half2*)&u3.w); v[6] = fmaf(a3, f.x, v[6]); v[7] = fmaf(a3, f.y, v[7]);

    if (valid) {
        float* op = &out[(size_t)dst * OUTC + 8 * j];
        red_add_v4(op,     make_float4(v[0], v[1], v[2], v[3]));
        red_add_v4(op + 4, make_float4(v[4], v[5], v[6], v[7]));
    }
}

// ---------------- 5) finalize ------------------------------------------------------
__global__ void final_kernel(float* __restrict__ out, const float* __restrict__ bias)
{
    int i = blockIdx.x * blockDim.x + threadIdx.x;
    if (i >= NN * OUTC) return;
    float v = out[i] + bias[i & (OUTC - 1)];
    out[i] = fmaxf(v, 0.0f);
}

// ---------------- launch --------------------------------------------------------
extern "C" void kernel_launch(void* const* d_in, const int* in_sizes, int n_in,
                              void* d_out, int out_size)
{
    const float* x       = (const float*)d_in[0];
    const void*  ei      = d_in[1];
    const float* W       = (const float*)d_in[2];
    const float* att_src = (const float*)d_in[3];
    const float* att_dst = (const float*)d_in[4];
    const float* bias    = (const float*)d_in[5];
    float* out = (float*)d_out;

    cudaFuncSetAttribute(gemm_tc_kernel,
                         cudaFuncAttributeMaxDynamicSharedMemorySize, GSMEM);

    prep_kernel<<<(HC * INC / 2 + 255) / 256, 256>>>(W);              // idx 0
    detect_kernel<<<1, 256>>>((const int*)ei);                        // idx 1
    gemm_tc_kernel<<<(NN + 127) / 128, 512, GSMEM>>>(x, att_src, att_dst); // idx 2
    edge_kernel<<<(ET + 255) / 256, 256>>>(ei, out);                  // idx 3
    scatter_kernel<<<((size_t)ET * 8 + 255) / 256, 256>>>(ei, out);   // idx 4
    final_kernel<<<(NN * OUTC + 255) / 256, 256>>>(out, bias);        // idx 5
}